// round 2
// baseline (speedup 1.0000x reference)
#include <cuda_runtime.h>

#define HID 64
#define IN_DIM 128
#define NMAX 100000

// Scratch (allocation-free rule: __device__ globals)
__device__ float g_p[NMAX * HID];
__device__ float g_agg[NMAX * HID];
__device__ float g_h1[NMAX * HID];

// ---------------------------------------------------------------------------
// GEMM: Y[M,64] = f(X) @ W[K,64]  (+ epilogue)
// CONSUME=false: x = X1[m][k];           Y = X@W;            also zero aggz rows
// CONSUME=true : x = relu(X1+X2+ba);     Y = leaky(X@W + bb)
// Tile: 64 rows x 64 cols per block, 256 threads, 4x4 register tile per thread
// ---------------------------------------------------------------------------
template <int K, bool CONSUME>
__global__ void gemm64_kernel(const float* __restrict__ X1,
                              const float* __restrict__ X2,
                              const float* __restrict__ ba,
                              const float* __restrict__ W,
                              const float* __restrict__ bb,
                              float* __restrict__ Y,
                              float* __restrict__ aggz,
                              int M) {
    constexpr int S = K + 4;       // padded Xs row stride (keeps 16B align, kills conflicts)
    constexpr int KC = K / 4;      // float4s per row
    extern __shared__ float smem[];
    float* Xs = smem;              // 64 * S floats
    float* Ws = smem + 64 * S;     // K * 64 floats (row-major, same layout as W)

    const int tid = threadIdx.x;
    const int m0 = blockIdx.x * 64;

    // Load W tile (K*64 floats, contiguous)
    for (int i = tid; i < K * 16; i += 256)
        ((float4*)Ws)[i] = ((const float4*)W)[i];

    // Load X tile with fused input transform
    for (int i = tid; i < 64 * KC; i += 256) {
        const int r = i / KC;
        const int kc = i % KC;
        const int m = m0 + r;
        float4 v = make_float4(0.f, 0.f, 0.f, 0.f);
        if (m < M) {
            v = ((const float4*)(X1 + (size_t)m * K))[kc];
            if (CONSUME) {
                float4 a = ((const float4*)(X2 + (size_t)m * K))[kc];
                float4 b = ((const float4*)ba)[kc];
                v.x = fmaxf(v.x + a.x + b.x, 0.f);
                v.y = fmaxf(v.y + a.y + b.y, 0.f);
                v.z = fmaxf(v.z + a.z + b.z, 0.f);
                v.w = fmaxf(v.w + a.w + b.w, 0.f);
            }
        }
        *(float4*)&Xs[r * S + kc * 4] = v;
    }
    __syncthreads();

    const int tx = tid & 15;   // column group: cols tx*4 .. tx*4+3
    const int ty = tid >> 4;   // row group:    rows ty*4 .. ty*4+3

    float acc[4][4];
#pragma unroll
    for (int i = 0; i < 4; i++)
#pragma unroll
        for (int j = 0; j < 4; j++) acc[i][j] = 0.f;

#pragma unroll 4
    for (int k = 0; k < K; k++) {
        float4 w = *(const float4*)&Ws[k * 64 + tx * 4];
        float x0 = Xs[(ty * 4 + 0) * S + k];
        float x1 = Xs[(ty * 4 + 1) * S + k];
        float x2 = Xs[(ty * 4 + 2) * S + k];
        float x3 = Xs[(ty * 4 + 3) * S + k];
        acc[0][0] += x0 * w.x; acc[0][1] += x0 * w.y; acc[0][2] += x0 * w.z; acc[0][3] += x0 * w.w;
        acc[1][0] += x1 * w.x; acc[1][1] += x1 * w.y; acc[1][2] += x1 * w.z; acc[1][3] += x1 * w.w;
        acc[2][0] += x2 * w.x; acc[2][1] += x2 * w.y; acc[2][2] += x2 * w.z; acc[2][3] += x2 * w.w;
        acc[3][0] += x3 * w.x; acc[3][1] += x3 * w.y; acc[3][2] += x3 * w.z; acc[3][3] += x3 * w.w;
    }

    float4 bias = make_float4(0.f, 0.f, 0.f, 0.f);
    if (CONSUME) bias = ((const float4*)bb)[tx];

#pragma unroll
    for (int i = 0; i < 4; i++) {
        const int m = m0 + ty * 4 + i;
        if (m < M) {
            float4 o;
            o.x = acc[i][0] + bias.x;
            o.y = acc[i][1] + bias.y;
            o.z = acc[i][2] + bias.z;
            o.w = acc[i][3] + bias.w;
            if (CONSUME) {
                o.x = o.x > 0.f ? o.x : 0.01f * o.x;
                o.y = o.y > 0.f ? o.y : 0.01f * o.y;
                o.z = o.z > 0.f ? o.z : 0.01f * o.z;
                o.w = o.w > 0.f ? o.w : 0.01f * o.w;
            }
            ((float4*)(Y + (size_t)m * 64))[tx] = o;
            if (!CONSUME)
                ((float4*)(aggz + (size_t)m * 64))[tx] = make_float4(0.f, 0.f, 0.f, 0.f);
        }
    }
}

// ---------------------------------------------------------------------------
// Edge scatter-add: agg[dst] += p[src], 64 floats per edge.
// 16 threads per edge, one float4 + one red.global.add.v4.f32 per thread.
// ---------------------------------------------------------------------------
__global__ void scatter64_kernel(const float* __restrict__ p,
                                 const int* __restrict__ src,
                                 const int* __restrict__ dst,
                                 float* __restrict__ agg,
                                 int E) {
    const int t = blockIdx.x * blockDim.x + threadIdx.x;
    const int e = t >> 4;
    if (e >= E) return;
    const int q = t & 15;
    const int s = __ldg(&src[e]);
    const int d = __ldg(&dst[e]);
    const float4 v = __ldg(((const float4*)(p + (size_t)s * 64)) + q);
    float* a = agg + (size_t)d * 64 + q * 4;
    asm volatile("red.global.add.v4.f32 [%0], {%1, %2, %3, %4};"
                 :: "l"(a), "f"(v.x), "f"(v.y), "f"(v.z), "f"(v.w)
                 : "memory");
}

// ---------------------------------------------------------------------------
extern "C" void kernel_launch(void* const* d_in, const int* in_sizes, int n_in,
                              void* d_out, int out_size) {
    const float* h   = (const float*)d_in[0];
    const int*   ei  = (const int*)d_in[1];
    const float* W1a = (const float*)d_in[2];
    const float* b1a = (const float*)d_in[3];
    const float* W1b = (const float*)d_in[4];
    const float* b1b = (const float*)d_in[5];
    const float* W2a = (const float*)d_in[6];
    const float* b2a = (const float*)d_in[7];
    const float* W2b = (const float*)d_in[8];
    const float* b2b = (const float*)d_in[9];
    float* out = (float*)d_out;

    const int M = in_sizes[0] / IN_DIM;   // 100000
    const int E = in_sizes[1] / 2;        // 1600000
    const int* src = ei;
    const int* dst = ei + E;

    float *p, *agg, *h1;
    cudaGetSymbolAddress((void**)&p,   g_p);
    cudaGetSymbolAddress((void**)&agg, g_agg);
    cudaGetSymbolAddress((void**)&h1,  g_h1);

    const int gblocks = (M + 63) / 64;
    const int sblocks = (E * 16 + 255) / 256;
    const int smem128 = (64 * (128 + 4) + 128 * 64) * 4;  // 66560 B
    const int smem64  = (64 * (64 + 4)  + 64 * 64)  * 4;  // 33792 B

    cudaFuncSetAttribute(gemm64_kernel<128, false>,
                         cudaFuncAttributeMaxDynamicSharedMemorySize, smem128);

    // ---- Layer 1 ----
    // p = h @ W1a   (bias b1a deferred; also zeroes agg)
    gemm64_kernel<128, false><<<gblocks, 256, smem128>>>(h, nullptr, nullptr,
                                                         W1a, nullptr, p, agg, M);
    // agg[dst] += p[src]
    scatter64_kernel<<<sblocks, 256>>>(p, src, dst, agg, E);
    // h1 = leaky( relu(p + agg + b1a) @ W1b + b1b )
    gemm64_kernel<64, true><<<gblocks, 256, smem64>>>(p, agg, b1a,
                                                      W1b, b1b, h1, nullptr, M);

    // ---- Layer 2 ----
    // p = h1 @ W2a   (zeroes agg)
    gemm64_kernel<64, false><<<gblocks, 256, smem64>>>(h1, nullptr, nullptr,
                                                       W2a, nullptr, p, agg, M);
    scatter64_kernel<<<sblocks, 256>>>(p, src, dst, agg, E);
    // out = leaky( relu(p + agg + b2a) @ W2b + b2b )
    gemm64_kernel<64, true><<<gblocks, 256, smem64>>>(p, agg, b2a,
                                                      W2b, b2b, out, nullptr, M);
}

// round 5
// speedup vs baseline: 1.1280x; 1.1280x over previous
#include <cuda_runtime.h>

#define HID 64
#define IN_DIM 128
#define NMAX 100000
#define EMAX 1600000

// Scratch (__device__ globals: allocation-free rule)
__device__ float g_p[NMAX * HID];
__device__ float g_agg[NMAX * HID];
__device__ float g_h1[NMAX * HID];
__device__ int   g_deg[NMAX];
__device__ int   g_row[NMAX + 1];
__device__ int   g_cur[NMAX];
__device__ int   g_blk[128];
__device__ int   g_blkoff[128];
__device__ int   g_adj[EMAX];

// ---------------------------------------------------------------------------
// CSR build kernels
// ---------------------------------------------------------------------------
__global__ void k_zero_deg(int* deg, int n) {
    int i = blockIdx.x * blockDim.x + threadIdx.x;
    if (i < n) deg[i] = 0;
}

__global__ void k_hist(const int* __restrict__ dst, int* deg, int E) {
    int i = blockIdx.x * blockDim.x + threadIdx.x;
    if (i < E) atomicAdd(&deg[dst[i]], 1);
}

// Per-block inclusive scan of deg (1024 elems/block) -> block-local exclusive
__global__ void k_scan1(const int* __restrict__ deg, int* row, int* blk, int M) {
    __shared__ int s[1024];
    int tid = threadIdx.x;
    int i = blockIdx.x * 1024 + tid;
    int v = (i < M) ? deg[i] : 0;
    s[tid] = v;
    __syncthreads();
#pragma unroll
    for (int off = 1; off < 1024; off <<= 1) {
        int t = (tid >= off) ? s[tid - off] : 0;
        __syncthreads();
        s[tid] += t;
        __syncthreads();
    }
    if (i < M) row[i] = s[tid] - v;          // block-local exclusive
    if (tid == 1023) blk[blockIdx.x] = s[1023];
}

// Single-block scan of block sums (nblk <= 128); also writes row[M] = total
__global__ void k_scan2(int* blk, int* blkoff, int* row, int nblk, int M) {
    __shared__ int s[128];
    int tid = threadIdx.x;
    int v = (tid < nblk) ? blk[tid] : 0;
    s[tid] = v;
    __syncthreads();
#pragma unroll
    for (int off = 1; off < 128; off <<= 1) {
        int t = (tid >= off) ? s[tid - off] : 0;
        __syncthreads();
        s[tid] += t;
        __syncthreads();
    }
    if (tid < nblk) blkoff[tid] = s[tid] - v;
    if (tid == 127) row[M] = s[127];
}

__global__ void k_scan3(int* row, int* cur, const int* __restrict__ blkoff, int M) {
    int i = blockIdx.x * blockDim.x + threadIdx.x;
    if (i < M) {
        int r = row[i] + blkoff[i >> 10];
        row[i] = r;
        cur[i] = r;
    }
}

__global__ void k_fill(const int* __restrict__ src, const int* __restrict__ dst,
                       int* cur, int* adj, int E) {
    int i = blockIdx.x * blockDim.x + threadIdx.x;
    if (i < E) {
        int pos = atomicAdd(&cur[dst[i]], 1);
        adj[pos] = src[i];
    }
}

// ---------------------------------------------------------------------------
// Gather-sum: agg[n] = sum_{j in row[n]..row[n+1]} p[adj[j]]   (64 floats/node)
// 16 threads per node, float4 per thread.
// ---------------------------------------------------------------------------
__global__ void k_gather(const float* __restrict__ p,
                         const int* __restrict__ row,
                         const int* __restrict__ adj,
                         float* __restrict__ agg, int M) {
    int t = blockIdx.x * blockDim.x + threadIdx.x;
    int n = t >> 4;
    if (n >= M) return;
    int q = t & 15;
    int beg = __ldg(&row[n]);
    int end = __ldg(&row[n + 1]);
    float4 s = make_float4(0.f, 0.f, 0.f, 0.f);
    for (int j = beg; j < end; j++) {
        int u = __ldg(&adj[j]);
        float4 v = __ldg(((const float4*)(p + (size_t)u * 64)) + q);
        s.x += v.x; s.y += v.y; s.z += v.z; s.w += v.w;
    }
    ((float4*)(agg + (size_t)n * 64))[q] = s;
}

// ---------------------------------------------------------------------------
// GEMM: Y[M,64] = f(X) @ W[K,64]
// CONSUME=false: x = X1;                  Y = X@W
// CONSUME=true : x = relu(X1+X2+ba);      Y = leaky(X@W + bb)
// Block tile 128x64, 128 threads, 8x8 register tile per thread.
// tx = tid&7: cols tx*8..+7; ty = tid>>3: rows ty + 16*i, i=0..7
// S = K+4 keeps every Xs row float4-aligned (STS.128 needs 16B alignment).
// ---------------------------------------------------------------------------
template <int K, bool CONSUME>
__global__ __launch_bounds__(128)
void gemm64_kernel(const float* __restrict__ X1,
                   const float* __restrict__ X2,
                   const float* __restrict__ ba,
                   const float* __restrict__ W,
                   const float* __restrict__ bb,
                   float* __restrict__ Y,
                   int M) {
    constexpr int S  = K + 4;     // multiple of 4: float4-aligned rows
    constexpr int KC = K / 4;
    extern __shared__ float smem[];
    float* Xs = smem;             // 128 * S
    float* Ws = smem + 128 * S;   // K * 64 (row-major, same layout as W)

    const int tid = threadIdx.x;
    const int m0  = blockIdx.x * 128;

    // Load W tile
    for (int i = tid; i < K * 16; i += 128)
        ((float4*)Ws)[i] = ((const float4*)W)[i];

    // Load X tile (fused transform)
    for (int i = tid; i < 128 * KC; i += 128) {
        const int r  = i / KC;
        const int kc = i % KC;
        const int m  = m0 + r;
        float4 v = make_float4(0.f, 0.f, 0.f, 0.f);
        if (m < M) {
            v = ((const float4*)(X1 + (size_t)m * K))[kc];
            if (CONSUME) {
                float4 a = ((const float4*)(X2 + (size_t)m * K))[kc];
                float4 b = ((const float4*)ba)[kc];
                v.x = fmaxf(v.x + a.x + b.x, 0.f);
                v.y = fmaxf(v.y + a.y + b.y, 0.f);
                v.z = fmaxf(v.z + a.z + b.z, 0.f);
                v.w = fmaxf(v.w + a.w + b.w, 0.f);
            }
        }
        *(float4*)&Xs[r * S + kc * 4] = v;
    }
    __syncthreads();

    const int tx = tid & 7;
    const int ty = tid >> 3;

    float acc[8][8];
#pragma unroll
    for (int i = 0; i < 8; i++)
#pragma unroll
        for (int j = 0; j < 8; j++) acc[i][j] = 0.f;

#pragma unroll 4
    for (int k = 0; k < K; k += 2) {
        const float4 wa0 = *(const float4*)&Ws[k * 64 + tx * 8];
        const float4 wa1 = *(const float4*)&Ws[k * 64 + tx * 8 + 4];
        const float4 wb0 = *(const float4*)&Ws[(k + 1) * 64 + tx * 8];
        const float4 wb1 = *(const float4*)&Ws[(k + 1) * 64 + tx * 8 + 4];
#pragma unroll
        for (int i = 0; i < 8; i++) {
            const float2 x = *(const float2*)&Xs[(ty + 16 * i) * S + k];
            acc[i][0] += x.x * wa0.x; acc[i][1] += x.x * wa0.y;
            acc[i][2] += x.x * wa0.z; acc[i][3] += x.x * wa0.w;
            acc[i][4] += x.x * wa1.x; acc[i][5] += x.x * wa1.y;
            acc[i][6] += x.x * wa1.z; acc[i][7] += x.x * wa1.w;
            acc[i][0] += x.y * wb0.x; acc[i][1] += x.y * wb0.y;
            acc[i][2] += x.y * wb0.z; acc[i][3] += x.y * wb0.w;
            acc[i][4] += x.y * wb1.x; acc[i][5] += x.y * wb1.y;
            acc[i][6] += x.y * wb1.z; acc[i][7] += x.y * wb1.w;
        }
    }

    float4 b0 = make_float4(0.f, 0.f, 0.f, 0.f);
    float4 b1 = make_float4(0.f, 0.f, 0.f, 0.f);
    if (CONSUME) {
        b0 = ((const float4*)bb)[tx * 2];
        b1 = ((const float4*)bb)[tx * 2 + 1];
    }

#pragma unroll
    for (int i = 0; i < 8; i++) {
        const int m = m0 + ty + 16 * i;
        if (m < M) {
            float4 o0, o1;
            o0.x = acc[i][0] + b0.x; o0.y = acc[i][1] + b0.y;
            o0.z = acc[i][2] + b0.z; o0.w = acc[i][3] + b0.w;
            o1.x = acc[i][4] + b1.x; o1.y = acc[i][5] + b1.y;
            o1.z = acc[i][6] + b1.z; o1.w = acc[i][7] + b1.w;
            if (CONSUME) {
                o0.x = o0.x > 0.f ? o0.x : 0.01f * o0.x;
                o0.y = o0.y > 0.f ? o0.y : 0.01f * o0.y;
                o0.z = o0.z > 0.f ? o0.z : 0.01f * o0.z;
                o0.w = o0.w > 0.f ? o0.w : 0.01f * o0.w;
                o1.x = o1.x > 0.f ? o1.x : 0.01f * o1.x;
                o1.y = o1.y > 0.f ? o1.y : 0.01f * o1.y;
                o1.z = o1.z > 0.f ? o1.z : 0.01f * o1.z;
                o1.w = o1.w > 0.f ? o1.w : 0.01f * o1.w;
            }
            float4* yr = (float4*)(Y + (size_t)m * 64);
            yr[tx * 2]     = o0;
            yr[tx * 2 + 1] = o1;
        }
    }
}

// ---------------------------------------------------------------------------
extern "C" void kernel_launch(void* const* d_in, const int* in_sizes, int n_in,
                              void* d_out, int out_size) {
    const float* h   = (const float*)d_in[0];
    const int*   ei  = (const int*)d_in[1];
    const float* W1a = (const float*)d_in[2];
    const float* b1a = (const float*)d_in[3];
    const float* W1b = (const float*)d_in[4];
    const float* b1b = (const float*)d_in[5];
    const float* W2a = (const float*)d_in[6];
    const float* b2a = (const float*)d_in[7];
    const float* W2b = (const float*)d_in[8];
    const float* b2b = (const float*)d_in[9];
    float* out = (float*)d_out;

    const int M = in_sizes[0] / IN_DIM;   // 100000
    const int E = in_sizes[1] / 2;        // 1600000
    const int* src = ei;
    const int* dst = ei + E;

    float *p, *agg, *h1;
    int *deg, *row, *cur, *blk, *blkoff, *adj;
    cudaGetSymbolAddress((void**)&p,      g_p);
    cudaGetSymbolAddress((void**)&agg,    g_agg);
    cudaGetSymbolAddress((void**)&h1,     g_h1);
    cudaGetSymbolAddress((void**)&deg,    g_deg);
    cudaGetSymbolAddress((void**)&row,    g_row);
    cudaGetSymbolAddress((void**)&cur,    g_cur);
    cudaGetSymbolAddress((void**)&blk,    g_blk);
    cudaGetSymbolAddress((void**)&blkoff, g_blkoff);
    cudaGetSymbolAddress((void**)&adj,    g_adj);

    const int nblk = (M + 1023) / 1024;

    // ---- CSR build (by dst), reused by both layers ----
    k_zero_deg<<<(M + 255) / 256, 256>>>(deg, M);
    k_hist<<<(E + 255) / 256, 256>>>(dst, deg, E);
    k_scan1<<<nblk, 1024>>>(deg, row, blk, M);
    k_scan2<<<1, 128>>>(blk, blkoff, row, nblk, M);
    k_scan3<<<(M + 255) / 256, 256>>>(row, cur, blkoff, M);
    k_fill<<<(E + 255) / 256, 256>>>(src, dst, cur, adj, E);

    const int gblocks = (M + 127) / 128;
    const int ablocks = (M * 16 + 255) / 256;
    const int smem128 = (128 * (128 + 4) + 128 * 64) * 4;  // 100352 B
    const int smem64  = (128 * (64 + 4)  + 64 * 64)  * 4;  // 51200 B

    cudaFuncSetAttribute(gemm64_kernel<128, false>,
                         cudaFuncAttributeMaxDynamicSharedMemorySize, smem128);
    cudaFuncSetAttribute(gemm64_kernel<64, false>,
                         cudaFuncAttributeMaxDynamicSharedMemorySize, smem64);
    cudaFuncSetAttribute(gemm64_kernel<64, true>,
                         cudaFuncAttributeMaxDynamicSharedMemorySize, smem64);

    // ---- Layer 1 ----
    gemm64_kernel<128, false><<<gblocks, 128, smem128>>>(h, nullptr, nullptr,
                                                         W1a, nullptr, p, M);
    k_gather<<<ablocks, 256>>>(p, row, adj, agg, M);
    gemm64_kernel<64, true><<<gblocks, 128, smem64>>>(p, agg, b1a,
                                                      W1b, b1b, h1, M);

    // ---- Layer 2 ----
    gemm64_kernel<64, false><<<gblocks, 128, smem64>>>(h1, nullptr, nullptr,
                                                       W2a, nullptr, p, M);
    k_gather<<<ablocks, 256>>>(p, row, adj, agg, M);
    gemm64_kernel<64, true><<<gblocks, 128, smem64>>>(p, agg, b2a,
                                                      W2b, b2b, out, M);
}